// round 3
// baseline (speedup 1.0000x reference)
#include <cuda_runtime.h>
#include <cuda_bf16.h>

#define N_NODES 50000
#define K_NBR 16
#define D 256
#define LN_EPS 1e-5f

// Scratch: weighted-gathered features x[N, 256] (51.2 MB). __device__ global
// because kernel_launch must be allocation-free.
__device__ __align__(16) float g_x[N_NODES * D];

// ---------------------------------------------------------------------------
// Kernel 1: x[n,:] = sum_k norm_w[n,k] * features[neighbors[n,k], :]
// 2 nodes per 128-thread block; 64 threads per node, one float4 per thread.
// Full unroll over K=16 -> 16 independent outstanding loads (MLP).
// NOTE: neighbors buffer is int32 (JAX x64 disabled downcasts the reference's
// jnp.int64 to int32).
// ---------------------------------------------------------------------------
__global__ __launch_bounds__(128) void gather_kernel(
    const float* __restrict__ features,
    const int* __restrict__ neighbors,
    const float* __restrict__ weights)
{
    const int half = threadIdx.x >> 6;   // 0 or 1: which node in this block
    const int t    = threadIdx.x & 63;   // 0..63: float4 lane within the row
    const int node = blockIdx.x * 2 + half;

    __shared__ float sw[2][K_NBR];
    __shared__ int   snb[2][K_NBR];

    if (node < N_NODES && t < K_NBR) {
        sw[half][t]  = weights[node * K_NBR + t];
        snb[half][t] = neighbors[node * K_NBR + t];
    }
    __syncthreads();
    if (node >= N_NODES) return;

    float wsum = 0.f;
#pragma unroll
    for (int k = 0; k < K_NBR; k++) wsum += sw[half][k];
    const bool zero = (wsum == 0.f);
    const float inv = zero ? 0.f : 1.f / wsum;

    const float4* __restrict__ f4 = (const float4*)features;
    float4 acc = make_float4(0.f, 0.f, 0.f, 0.f);

#pragma unroll
    for (int k = 0; k < K_NBR; k++) {
        const float w = zero ? (1.f / (float)K_NBR) : sw[half][k] * inv;
        const float4 v = f4[(size_t)snb[half][k] * (D / 4) + t];
        acc.x += w * v.x;
        acc.y += w * v.y;
        acc.z += w * v.z;
        acc.w += w * v.w;
    }
    ((float4*)g_x)[(size_t)node * (D / 4) + t] = acc;
}

// ---------------------------------------------------------------------------
// Kernel 2: out = LayerNorm(x @ W + b) * gamma + beta
// Block tile: 64 rows x 256 cols (full output width -> LN fuses in-block).
// 256 threads; thread microtile 8x8. Thread (ty = tid/32, tx = tid%32):
// rows ty*8..ty*8+7, cols tx*8..tx*8+7. One warp owns one 8-row group, so
// LN row reductions are pure warp shuffles.
// ---------------------------------------------------------------------------
#define MT 64
#define KT 16
#define AP 68   // padded leading dim for As (16B-aligned rows, conflict-lite)

__global__ __launch_bounds__(256) void gemm_ln_kernel(
    const float* __restrict__ W,      // [D_in=256, D_out=256] row-major
    const float* __restrict__ bias,   // [256]
    const float* __restrict__ gamma,  // [256]
    const float* __restrict__ beta,   // [256]
    float* __restrict__ out)          // [N, 256]
{
    __shared__ float As[KT][AP];   // As[k][row]  (A stored transposed)
    __shared__ float Bs[KT][D];    // Bs[k][col]

    const int tid = threadIdx.x;
    const int tx  = tid & 31;   // column group
    const int ty  = tid >> 5;   // row group (0..7) == warp id
    const int rb  = blockIdx.x * MT;

    float acc[8][8];
#pragma unroll
    for (int i = 0; i < 8; i++)
#pragma unroll
        for (int j = 0; j < 8; j++) acc[i][j] = 0.f;

    // A-tile load mapping: 64 rows x 16 k-cols, one float4 per thread
    const int arow = tid >> 2;         // 0..63
    const int ac   = (tid & 3) * 4;    // 0,4,8,12
    const int grow_a = rb + arow;
    const bool arow_ok = (grow_a < N_NODES);

    for (int kc = 0; kc < D; kc += KT) {
        // ---- load A tile (transposed into As[k][row]) ----
        float4 av = make_float4(0.f, 0.f, 0.f, 0.f);
        if (arow_ok)
            av = *(const float4*)&g_x[(size_t)grow_a * D + kc + ac];
        As[ac + 0][arow] = av.x;
        As[ac + 1][arow] = av.y;
        As[ac + 2][arow] = av.z;
        As[ac + 3][arow] = av.w;

        // ---- load B tile: 16 rows x 256 cols, coalesced float4 ----
#pragma unroll
        for (int r = 0; r < 4; r++) {
            const int brow = r * 4 + (tid >> 6);     // 0..15
            const int bcol = (tid & 63) * 4;         // 0..252
            *(float4*)&Bs[brow][bcol] =
                *(const float4*)&W[(size_t)(kc + brow) * D + bcol];
        }
        __syncthreads();

        // ---- MAC ----
#pragma unroll
        for (int k = 0; k < KT; k++) {
            float a[8];
#pragma unroll
            for (int i = 0; i < 8; i++) a[i] = As[k][ty * 8 + i];  // broadcast
            const float4 b0 = *(const float4*)&Bs[k][tx * 8];
            const float4 b1 = *(const float4*)&Bs[k][tx * 8 + 4];
            const float bv[8] = {b0.x, b0.y, b0.z, b0.w, b1.x, b1.y, b1.z, b1.w};
#pragma unroll
            for (int i = 0; i < 8; i++)
#pragma unroll
                for (int j = 0; j < 8; j++)
                    acc[i][j] = fmaf(a[i], bv[j], acc[i][j]);
        }
        __syncthreads();
    }

    // ---- epilogue: bias + LayerNorm + affine ----
    const float4 bb0 = *(const float4*)&bias[tx * 8];
    const float4 bb1 = *(const float4*)&bias[tx * 8 + 4];
    const float bval[8] = {bb0.x, bb0.y, bb0.z, bb0.w, bb1.x, bb1.y, bb1.z, bb1.w};
    const float4 gg0 = *(const float4*)&gamma[tx * 8];
    const float4 gg1 = *(const float4*)&gamma[tx * 8 + 4];
    const float gval[8] = {gg0.x, gg0.y, gg0.z, gg0.w, gg1.x, gg1.y, gg1.z, gg1.w};
    const float4 ee0 = *(const float4*)&beta[tx * 8];
    const float4 ee1 = *(const float4*)&beta[tx * 8 + 4];
    const float eval_[8] = {ee0.x, ee0.y, ee0.z, ee0.w, ee1.x, ee1.y, ee1.z, ee1.w};

#pragma unroll
    for (int i = 0; i < 8; i++) {
        float s1 = 0.f, s2 = 0.f;
#pragma unroll
        for (int j = 0; j < 8; j++) {
            const float v = acc[i][j] + bval[j];
            acc[i][j] = v;
            s1 += v;
            s2 += v * v;
        }
        // warp-wide reduction over the 32 column-threads of this row
#pragma unroll
        for (int off = 16; off > 0; off >>= 1) {
            s1 += __shfl_xor_sync(0xffffffffu, s1, off);
            s2 += __shfl_xor_sync(0xffffffffu, s2, off);
        }
        const float mean = s1 * (1.f / (float)D);
        const float var  = s2 * (1.f / (float)D) - mean * mean;
        const float rstd = rsqrtf(var + LN_EPS);

        const int grow = rb + ty * 8 + i;
        if (grow < N_NODES) {
            float o[8];
#pragma unroll
            for (int j = 0; j < 8; j++)
                o[j] = (acc[i][j] - mean) * rstd * gval[j] + eval_[j];
            float* dst = &out[(size_t)grow * D + tx * 8];
            *(float4*)dst       = make_float4(o[0], o[1], o[2], o[3]);
            *(float4*)(dst + 4) = make_float4(o[4], o[5], o[6], o[7]);
        }
    }
}

// ---------------------------------------------------------------------------
// Launch. Input order (metadata): features, neighbors, importance_weights,
// W, b, gamma, beta. Output: float [50000, 256].
// ---------------------------------------------------------------------------
extern "C" void kernel_launch(void* const* d_in, const int* in_sizes, int n_in,
                              void* d_out, int out_size)
{
    const float* features  = (const float*)d_in[0];
    const int*   neighbors = (const int*)d_in[1];
    const float* weights   = (const float*)d_in[2];
    const float* W         = (const float*)d_in[3];
    const float* bias      = (const float*)d_in[4];
    const float* gamma     = (const float*)d_in[5];
    const float* beta      = (const float*)d_in[6];
    float*       out       = (float*)d_out;

    gather_kernel<<<(N_NODES + 1) / 2, 128>>>(features, neighbors, weights);
    gemm_ln_kernel<<<(N_NODES + MT - 1) / MT, 256>>>(W, bias, gamma, beta, out);
}

// round 6
// speedup vs baseline: 1.8210x; 1.8210x over previous
#include <cuda_runtime.h>
#include <cuda_bf16.h>
#include <cstdint>

#define N_NODES 50000
#define K_NBR 16
#define D 256
#define LN_EPS 1e-5f
#define MROWS 128
#define NBLOCKS ((N_NODES + MROWS - 1) / MROWS)

// ---------------------------------------------------------------------------
// Device-global scratch (allocation-free rule)
// ---------------------------------------------------------------------------
__device__ __align__(16) __nv_bfloat16 g_xhi[N_NODES * D];   // 25.6 MB
__device__ __align__(16) __nv_bfloat16 g_xlo[N_NODES * D];   // 25.6 MB
__device__ __align__(16) __nv_bfloat16 g_wthi[D * D];        // W^T hi [n][k]
__device__ __align__(16) __nv_bfloat16 g_wtlo[D * D];        // W^T lo [n][k]

// ---------------------------------------------------------------------------
// PTX helpers (all baseline sm_80+ — compile at virtual compute_103)
// ---------------------------------------------------------------------------
__device__ __forceinline__ uint32_t smem_to_u32(const void* p) {
    uint32_t a;
    asm("{ .reg .u64 t; cvta.to.shared.u64 t, %1; cvt.u32.u64 %0, t; }"
        : "=r"(a) : "l"(p));
    return a;
}

#define CP_ASYNC16(dst, src, szz) \
    asm volatile("cp.async.cg.shared.global [%0], [%1], 16, %2;" \
                 :: "r"(dst), "l"(src), "r"(szz) : "memory")
#define CP_COMMIT() asm volatile("cp.async.commit_group;" ::: "memory")
#define CP_WAIT(n)  asm volatile("cp.async.wait_group %0;" :: "n"(n) : "memory")

#define LDSM_X4(d, addr) \
    asm volatile("ldmatrix.sync.aligned.m8n8.x4.shared.b16 {%0,%1,%2,%3}, [%4];" \
                 : "=r"((d)[0]), "=r"((d)[1]), "=r"((d)[2]), "=r"((d)[3]) \
                 : "r"(addr))

__device__ __forceinline__ void mma16816(float c[4], const uint32_t a[4],
                                         uint32_t b0, uint32_t b1) {
    asm volatile(
        "mma.sync.aligned.m16n8k16.row.col.f32.bf16.bf16.f32 "
        "{%0,%1,%2,%3}, {%4,%5,%6,%7}, {%8,%9}, {%0,%1,%2,%3};"
        : "+f"(c[0]), "+f"(c[1]), "+f"(c[2]), "+f"(c[3])
        : "r"(a[0]), "r"(a[1]), "r"(a[2]), "r"(a[3]), "r"(b0), "r"(b1));
}

// ---------------------------------------------------------------------------
// SMEM layout (dynamic, 200 KB)
//   stage s (s=0,1) at s*98304:
//     A_HI +0     (128 rows x 128 B, swizzled)  16 KB
//     A_LO +16384                               16 KB
//     B_HI +32768 (256 rows x 128 B, swizzled)  32 KB
//     B_LO +65536                               32 KB
// ---------------------------------------------------------------------------
#define STAGE_SZ   98304
#define OFF_A_HI   0
#define OFF_A_LO   16384
#define OFF_B_HI   32768
#define OFF_B_LO   65536
#define OFF_BIAS   196608
#define OFF_GAMMA  197632
#define OFF_BETA   198656
#define OFF_RED    199680   // float2 red[128][4]  = 4 KB
#define OFF_STAT   203776   // float2 stat[128]    = 1 KB
#define SMEM_TOTAL 204800

// ---------------------------------------------------------------------------
// Kernel 0: W [D_in, D_out] -> W^T bf16 hi/lo ([n][k], K-contiguous)
// ---------------------------------------------------------------------------
__global__ __launch_bounds__(256) void prep_w(const float* __restrict__ W) {
    const int n = blockIdx.x;
    const int k = threadIdx.x;
    const float v = W[k * D + n];
    const __nv_bfloat16 hi = __float2bfloat16(v);
    const __nv_bfloat16 lo = __float2bfloat16(v - __bfloat162float(hi));
    g_wthi[n * D + k] = hi;
    g_wtlo[n * D + k] = lo;
}

// ---------------------------------------------------------------------------
// Kernel 1: weighted gather -> x_hi/x_lo bf16 (neighbors are int32)
// ---------------------------------------------------------------------------
__global__ __launch_bounds__(128) void gather_kernel(
    const float* __restrict__ features,
    const int* __restrict__ neighbors,
    const float* __restrict__ weights)
{
    const int half = threadIdx.x >> 6;
    const int t    = threadIdx.x & 63;
    const int node = blockIdx.x * 2 + half;

    __shared__ float sw[2][K_NBR];
    __shared__ int   snb[2][K_NBR];

    if (node < N_NODES && t < K_NBR) {
        sw[half][t]  = weights[node * K_NBR + t];
        snb[half][t] = neighbors[node * K_NBR + t];
    }
    __syncthreads();
    if (node >= N_NODES) return;

    float wsum = 0.f;
#pragma unroll
    for (int k = 0; k < K_NBR; k++) wsum += sw[half][k];
    const bool zero = (wsum == 0.f);
    const float inv = zero ? 0.f : 1.f / wsum;

    const float4* __restrict__ f4 = (const float4*)features;
    float4 acc = make_float4(0.f, 0.f, 0.f, 0.f);

#pragma unroll
    for (int k = 0; k < K_NBR; k++) {
        const float w = zero ? (1.f / (float)K_NBR) : sw[half][k] * inv;
        const float4 v = f4[(size_t)snb[half][k] * (D / 4) + t];
        acc.x += w * v.x;
        acc.y += w * v.y;
        acc.z += w * v.z;
        acc.w += w * v.w;
    }

    __nv_bfloat16 h[4], l[4];
    h[0] = __float2bfloat16(acc.x); l[0] = __float2bfloat16(acc.x - __bfloat162float(h[0]));
    h[1] = __float2bfloat16(acc.y); l[1] = __float2bfloat16(acc.y - __bfloat162float(h[1]));
    h[2] = __float2bfloat16(acc.z); l[2] = __float2bfloat16(acc.z - __bfloat162float(h[2]));
    h[3] = __float2bfloat16(acc.w); l[3] = __float2bfloat16(acc.w - __bfloat162float(h[3]));

    const size_t off = (size_t)node * D + t * 4;
    *(uint2*)&g_xhi[off] = *(uint2*)h;
    *(uint2*)&g_xlo[off] = *(uint2*)l;
}

// ---------------------------------------------------------------------------
// Stage one K-chunk (64 k) of A (hi/lo) and B (hi/lo) via cp.async.
// Swizzle: byte = row*128 + u*16  ->  byte ^ ((row&7)*16)
// ---------------------------------------------------------------------------
__device__ __forceinline__ void stage_chunk(int c, uint32_t sbase, int rb, int tid)
{
#pragma unroll
    for (int i = 0; i < 4; i++) {            // A: 128 rows x 8 chunks
        const int e   = i * 256 + tid;
        const int row = e >> 3;
        const int u   = e & 7;
        const uint32_t dst = sbase + OFF_A_HI
                           + ((uint32_t)(row * 128 + u * 16) ^ (uint32_t)((row & 7) * 16));
        const int grow = rb + row;
        const int sz = (grow < N_NODES) ? 16 : 0;
        const size_t goff = (size_t)grow * D + c * 64 + u * 8;
        CP_ASYNC16(dst,             (const char*)&g_xhi[goff], sz);
        CP_ASYNC16(dst + 16384u,    (const char*)&g_xlo[goff], sz);
    }
#pragma unroll
    for (int i = 0; i < 8; i++) {            // B: 256 n-rows x 8 chunks
        const int e = i * 256 + tid;
        const int n = e >> 3;
        const int u = e & 7;
        const uint32_t dst = sbase + OFF_B_HI
                           + ((uint32_t)(n * 128 + u * 16) ^ (uint32_t)((n & 7) * 16));
        const size_t goff = (size_t)n * D + c * 64 + u * 8;
        CP_ASYNC16(dst,             (const char*)&g_wthi[goff], 16);
        CP_ASYNC16(dst + 32768u,    (const char*)&g_wtlo[goff], 16);
    }
}

// ---------------------------------------------------------------------------
// Kernel 2: mma.sync bf16 GEMM (3-term split, fp32 accum) + fused LayerNorm.
// 256 threads = 8 warps (2 row-groups x 4 col-groups); warp tile 64m x 64n.
// ---------------------------------------------------------------------------
__global__ __launch_bounds__(256, 1) void gemm_ln_mma(
    const float* __restrict__ bias,
    const float* __restrict__ gamma,
    const float* __restrict__ beta,
    float* __restrict__ out)
{
    extern __shared__ char smem[];
    const uint32_t smem_u32 = smem_to_u32(smem);
    const int tid  = threadIdx.x;
    const int warp = tid >> 5;
    const int lid  = tid & 31;
    const int wr   = warp >> 2;   // 0..1  (rows wr*64 .. +63)
    const int wc   = warp & 3;    // 0..3  (cols wc*64 .. +63)
    const int grp  = lid >> 3;    // ldmatrix address group
    const int idx  = lid & 7;
    const int rb   = blockIdx.x * MROWS;

    // params -> smem
    for (int i = tid; i < D; i += 256) {
        *(float*)(smem + OFF_BIAS  + i * 4) = bias[i];
        *(float*)(smem + OFF_GAMMA + i * 4) = gamma[i];
        *(float*)(smem + OFF_BETA  + i * 4) = beta[i];
    }

    float acc[4][8][4];
#pragma unroll
    for (int mt = 0; mt < 4; mt++)
#pragma unroll
        for (int nt = 0; nt < 8; nt++)
#pragma unroll
            for (int q = 0; q < 4; q++) acc[mt][nt][q] = 0.f;

    // ldmatrix lane bases
    // A frag (m16k16): r0 rows+0 kh0 | r1 rows+8 kh0 | r2 rows+0 kh1 | r3 rows+8 kh1
    const int a_kh = grp >> 1;
    uint32_t a_base[4];
#pragma unroll
    for (int mt = 0; mt < 4; mt++)
        a_base[mt] = (uint32_t)((wr * 64 + mt * 16 + (grp & 1) * 8 + idx) * 128);
    // B frag pair (2 n-tiles): r0 n+0 kh0 | r1 n+0 kh1 | r2 n+8 kh0 | r3 n+8 kh1
    const int b_kh = grp & 1;
    uint32_t b_base[4];
#pragma unroll
    for (int p = 0; p < 4; p++)
        b_base[p] = (uint32_t)((wc * 64 + p * 16 + (grp >> 1) * 8 + idx) * 128);
    const uint32_t xorv = (uint32_t)(idx * 16);

    // ---- 2-stage cp.async pipeline over 4 K-chunks ----
    stage_chunk(0, smem_u32, rb, tid);
    CP_COMMIT();

    for (int c = 0; c < 4; c++) {
        if (c < 3) {
            stage_chunk(c + 1, smem_u32 + ((c + 1) & 1) * STAGE_SZ, rb, tid);
            CP_COMMIT();
            CP_WAIT(1);
        } else {
            CP_WAIT(0);
        }
        __syncthreads();

        const uint32_t sbase = smem_u32 + (c & 1) * STAGE_SZ;

#pragma unroll
        for (int ks = 0; ks < 4; ks++) {
            const uint32_t xa = (uint32_t)(ks * 32 + a_kh * 16) ^ xorv;
            const uint32_t xb = (uint32_t)(ks * 32 + b_kh * 16) ^ xorv;

            uint32_t ah[4][4], al[4][4];
#pragma unroll
            for (int mt = 0; mt < 4; mt++) {
                const uint32_t aaddr = sbase + OFF_A_HI + a_base[mt] + xa;
                LDSM_X4(ah[mt], aaddr);
                LDSM_X4(al[mt], aaddr + 16384u);
            }
#pragma unroll
            for (int p = 0; p < 4; p++) {
                uint32_t bh[4], bl[4];
                const uint32_t baddr = sbase + OFF_B_HI + b_base[p] + xb;
                LDSM_X4(bh, baddr);
                LDSM_X4(bl, baddr + 32768u);
#pragma unroll
                for (int h = 0; h < 2; h++) {
                    const int nt = p * 2 + h;
                    const uint32_t b0h = bh[h * 2], b1h = bh[h * 2 + 1];
                    const uint32_t b0l = bl[h * 2], b1l = bl[h * 2 + 1];
#pragma unroll
                    for (int mt = 0; mt < 4; mt++) {
                        mma16816(acc[mt][nt], ah[mt], b0h, b1h);
                        mma16816(acc[mt][nt], al[mt], b0h, b1h);
                        mma16816(acc[mt][nt], ah[mt], b0l, b1l);
                    }
                }
            }
        }
        __syncthreads();
    }

    // ---- epilogue: bias + LayerNorm + affine ----
    const float* bias_s  = (const float*)(smem + OFF_BIAS);
    const float* gamma_s = (const float*)(smem + OFF_GAMMA);
    const float* beta_s  = (const float*)(smem + OFF_BETA);
    float2* red  = (float2*)(smem + OFF_RED);    // red[row*4 + wc]
    float2* stat = (float2*)(smem + OFF_STAT);   // stat[row] = (mean, rstd)

    // bias add in place
#pragma unroll
    for (int mt = 0; mt < 4; mt++)
#pragma unroll
        for (int nt = 0; nt < 8; nt++) {
            const int col = wc * 64 + nt * 8 + (lid & 3) * 2;
            acc[mt][nt][0] += bias_s[col];
            acc[mt][nt][1] += bias_s[col + 1];
            acc[mt][nt][2] += bias_s[col];
            acc[mt][nt][3] += bias_s[col + 1];
        }

    // per-thread partial sums for 8 rows (mt x {g, g+8})
    float s1[8], s2[8];
#pragma unroll
    for (int mt = 0; mt < 4; mt++) {
        float a1 = 0.f, a2 = 0.f, b1 = 0.f, b2 = 0.f;
#pragma unroll
        for (int nt = 0; nt < 8; nt++) {
            a1 += acc[mt][nt][0] + acc[mt][nt][1];
            a2 += acc[mt][nt][0] * acc[mt][nt][0] + acc[mt][nt][1] * acc[mt][nt][1];
            b1 += acc[mt][nt][2] + acc[mt][nt][3];
            b2 += acc[mt][nt][2] * acc[mt][nt][2] + acc[mt][nt][3] * acc[mt][nt][3];
        }
        s1[mt * 2] = a1; s2[mt * 2] = a2;
        s1[mt * 2 + 1] = b1; s2[mt * 2 + 1] = b2;
    }
    // reduce over the 4 column-lanes (t%4)
#pragma unroll
    for (int z = 1; z <= 2; z <<= 1)
#pragma unroll
        for (int i = 0; i < 8; i++) {
            s1[i] += __shfl_xor_sync(0xffffffffu, s1[i], z);
            s2[i] += __shfl_xor_sync(0xffffffffu, s2[i], z);
        }

    if ((lid & 3) == 0) {
        const int g = lid >> 2;
#pragma unroll
        for (int mt = 0; mt < 4; mt++)
#pragma unroll
            for (int h = 0; h < 2; h++) {
                const int row = wr * 64 + mt * 16 + h * 8 + g;
                red[row * 4 + wc] = make_float2(s1[mt * 2 + h], s2[mt * 2 + h]);
            }
    }
    __syncthreads();

    if (tid < MROWS) {
        float t1 = 0.f, t2 = 0.f;
#pragma unroll
        for (int w = 0; w < 4; w++) {
            const float2 v = red[tid * 4 + w];
            t1 += v.x; t2 += v.y;
        }
        const float mean = t1 * (1.f / (float)D);
        const float var  = t2 * (1.f / (float)D) - mean * mean;
        stat[tid] = make_float2(mean, rsqrtf(var + LN_EPS));
    }
    __syncthreads();

    // normalize + store
    const int g = lid >> 2;
#pragma unroll
    for (int mt = 0; mt < 4; mt++) {
        const int r0 = wr * 64 + mt * 16 + g;
        const int r1 = r0 + 8;
        const float2 st0 = stat[r0];
        const float2 st1 = stat[r1];
#pragma unroll
        for (int nt = 0; nt < 8; nt++) {
            const int col = wc * 64 + nt * 8 + (lid & 3) * 2;
            const float gm0 = gamma_s[col], gm1 = gamma_s[col + 1];
            const float bt0 = beta_s[col],  bt1 = beta_s[col + 1];
            if (rb + r0 < N_NODES) {
                float2 o;
                o.x = (acc[mt][nt][0] - st0.x) * st0.y * gm0 + bt0;
                o.y = (acc[mt][nt][1] - st0.x) * st0.y * gm1 + bt1;
                *(float2*)&out[(size_t)(rb + r0) * D + col] = o;
            }
            if (rb + r1 < N_NODES) {
                float2 o;
                o.x = (acc[mt][nt][2] - st1.x) * st1.y * gm0 + bt0;
                o.y = (acc[mt][nt][3] - st1.x) * st1.y * gm1 + bt1;
                *(float2*)&out[(size_t)(rb + r1) * D + col] = o;
            }
        }
    }
}

// ---------------------------------------------------------------------------
// Launch
// ---------------------------------------------------------------------------
extern "C" void kernel_launch(void* const* d_in, const int* in_sizes, int n_in,
                              void* d_out, int out_size)
{
    const float* features  = (const float*)d_in[0];
    const int*   neighbors = (const int*)d_in[1];
    const float* weights   = (const float*)d_in[2];
    const float* W         = (const float*)d_in[3];
    const float* bias      = (const float*)d_in[4];
    const float* gamma     = (const float*)d_in[5];
    const float* beta      = (const float*)d_in[6];
    float*       out       = (float*)d_out;

    cudaFuncSetAttribute(gemm_ln_mma,
                         cudaFuncAttributeMaxDynamicSharedMemorySize, SMEM_TOTAL);

    prep_w<<<D, D>>>(W);
    gather_kernel<<<(N_NODES + 1) / 2, 128>>>(features, neighbors, weights);
    gemm_ln_mma<<<NBLOCKS, 256, SMEM_TOTAL>>>(bias, gamma, beta, out);
}